// round 7
// baseline (speedup 1.0000x reference)
#include <cuda_runtime.h>
#include <math.h>

#define HH 128
#define WW 128
#define HWSZ (HH*WW)
#define NFC 64
#define BB 4

// Scratch ping-pong buffers (no allocation allowed)
__device__ float g_bufA[BB*NFC*HWSZ];
__device__ float g_bufB[BB*NFC*HWSZ];

// ---------------------------------------------------------------------------
// Tiled 3x3 conv, stride 1, pad 1. (unchanged from R6 baseline)
// ---------------------------------------------------------------------------
__global__ __launch_bounds__(128) void conv3x3_k(
    const float* __restrict__ in0, const float* __restrict__ in1, int cin,
    const float* __restrict__ wgt, const float* __restrict__ bias,
    float* __restrict__ out, int cout, int mode,
    float* __restrict__ outOff, float* __restrict__ outMask)
{
    __shared__ float s_in[8][18][34];   // [ci][row 16+2][col 32+2]
    __shared__ float s_w[8][8][9];      // [oc][ci][k]

    const int tx = threadIdx.x;         // 0..7
    const int ty = threadIdx.y;         // 0..15
    const int tid = ty * 8 + tx;
    const int x0 = blockIdx.x * 32;
    const int y0 = blockIdx.y * 16;
    const int groups = (cout + 7) / 8;
    const int b = blockIdx.z / groups;
    const int ocBase = (blockIdx.z % groups) * 8;

    float acc[8][4];
#pragma unroll
    for (int o = 0; o < 8; o++)
#pragma unroll
        for (int p = 0; p < 4; p++) acc[o][p] = 0.f;

    for (int cb = 0; cb < cin; cb += 8) {
        __syncthreads();
        for (int idx = tid; idx < 8 * 612; idx += 128) {
            int ci = idx / 612;
            int rem = idx % 612;
            int r = rem / 34;
            int c = rem % 34;
            int gy = y0 + r - 1;
            int gx = x0 + c - 1;
            int ch = cb + ci;
            const float* src = in0;
            int chl = ch;
            if (ch >= 64) { src = in1; chl = ch - 64; }
            float v = 0.f;
            if (gy >= 0 && gy < HH && gx >= 0 && gx < WW)
                v = __ldg(&src[((b * 64 + chl) * HH + gy) * WW + gx]);
            (&s_in[0][0][0])[idx] = v;
        }
        for (int idx = tid; idx < 8 * 8 * 9; idx += 128) {
            int oc = idx / 72;
            int rem = idx % 72;
            int ci = rem / 9;
            int k = rem % 9;
            int gc = ocBase + oc;
            float v = 0.f;
            if (gc < cout) v = __ldg(&wgt[(gc * cin + cb + ci) * 9 + k]);
            (&s_w[0][0][0])[idx] = v;
        }
        __syncthreads();

#pragma unroll 2
        for (int ci = 0; ci < 8; ci++) {
            float v[3][6];
#pragma unroll
            for (int r = 0; r < 3; r++)
#pragma unroll
                for (int c = 0; c < 6; c++)
                    v[r][c] = s_in[ci][ty + r][tx * 4 + c];
#pragma unroll
            for (int oc = 0; oc < 8; oc++) {
#pragma unroll
                for (int kr = 0; kr < 3; kr++)
#pragma unroll
                    for (int kc = 0; kc < 3; kc++) {
                        float wv = s_w[oc][ci][kr * 3 + kc];
#pragma unroll
                        for (int p = 0; p < 4; p++)
                            acc[oc][p] = fmaf(v[kr][kc + p], wv, acc[oc][p]);
                    }
            }
        }
    }

    const int y = y0 + ty;
    const int xb = x0 + tx * 4;
#pragma unroll
    for (int oc = 0; oc < 8; oc++) {
        int gc = ocBase + oc;
        if (gc >= cout) continue;
        float bv = __ldg(&bias[gc]);
        float r[4];
#pragma unroll
        for (int p = 0; p < 4; p++) r[p] = acc[oc][p] + bv;
        if (mode == 0) {
#pragma unroll
            for (int p = 0; p < 4; p++) r[p] = (r[p] >= 0.f) ? r[p] : 0.1f * r[p];
            float4 v4 = make_float4(r[0], r[1], r[2], r[3]);
            *(float4*)&out[((b * cout + gc) * HH + y) * WW + xb] = v4;
        } else {
            if (gc < 18) {
#pragma unroll
                for (int p = 0; p < 4; p++) r[p] = 15.f * tanhf(r[p]);
                float4 v4 = make_float4(r[0], r[1], r[2], r[3]);
                *(float4*)&outOff[((b * 18 + gc) * HH + y) * WW + xb] = v4;
            } else {
#pragma unroll
                for (int p = 0; p < 4; p++) r[p] = 1.f / (1.f + expf(-r[p]));
                float4 v4 = make_float4(r[0], r[1], r[2], r[3]);
                *(float4*)&outMask[((b * 9 + (gc - 18)) * HH + y) * WW + xb] = v4;
            }
        }
    }
}

// ---------------------------------------------------------------------------
// DCNv2 as smem-staged implicit GEMM.
// Block: 256 threads, 2 rows x 128 px, ALL 64 oc.
// Phase A: bilinear tables (pre-masked corner weights + clamped coords).
// Per 4-channel chunk: cooperative gather -> s_samp[36][256], then
// register-tiled GEMM: thread = 16 oc x 4 px.
// Dynamic smem = 101376 B -> 2 blocks/SM.
// ---------------------------------------------------------------------------
__global__ __launch_bounds__(256, 2) void dcn_gemm_k(
    const float* __restrict__ xin, const float* __restrict__ off,
    const float* __restrict__ msk, const float* __restrict__ wgt,
    const float* __restrict__ bias, float* __restrict__ out)
{
    extern __shared__ float sm[];
    float*   s_tabw = sm;                          // 9*256 float4  = 36864 B
    ushort4* s_tabi = (ushort4*)(sm + 9216);       // 9*256 ushort4 = 18432 B
    float*   s_samp = sm + 9216 + 4608;            // 36*256 floats = 36864 B
    float*   s_w    = s_samp + 9216;               // 36*64 floats  =  9216 B

    const int tid  = threadIdx.x;
    const int b    = blockIdx.y;
    const int row0 = blockIdx.x * 2;

    // ---- Phase A: bilinear tables, one (px, tap) entry per thread-iteration
    {
        const int x = tid & 127;
        const int y = row0 + (tid >> 7);
#pragma unroll
        for (int k = 0; k < 9; k++) {
            float oy = __ldg(&off[((b * 18 + 2 * k) * HH + y) * WW + x]);
            float ox = __ldg(&off[((b * 18 + 2 * k + 1) * HH + y) * WW + x]);
            float m  = __ldg(&msk[((b * 9 + k) * HH + y) * WW + x]);
            float py  = (float)(y + k / 3 - 1) + oy;
            float pxf = (float)(x + k % 3 - 1) + ox;
            float fy = floorf(py);
            float fx = floorf(pxf);
            float wy = py - fy;
            float wx = pxf - fx;
            int iy = (int)fy;
            int ix = (int)fx;
            bool vy0 = ((unsigned)iy) < 128u;
            bool vy1 = ((unsigned)(iy + 1)) < 128u;
            bool vx0 = ((unsigned)ix) < 128u;
            bool vx1 = ((unsigned)(ix + 1)) < 128u;
            float w00 = (1.f - wy) * (1.f - wx) * m;
            float w01 = (1.f - wy) * wx * m;
            float w10 = wy * (1.f - wx) * m;
            float w11 = wy * wx * m;
            if (!(vy0 && vx0)) w00 = 0.f;
            if (!(vy0 && vx1)) w01 = 0.f;
            if (!(vy1 && vx0)) w10 = 0.f;
            if (!(vy1 && vx1)) w11 = 0.f;
            ((float4*)s_tabw)[k * 256 + tid] = make_float4(w00, w01, w10, w11);
            unsigned short xA = (unsigned short)min(max(ix, 0), 127);
            unsigned short xB = (unsigned short)min(max(ix + 1, 0), 127);
            unsigned short yA = (unsigned short)(min(max(iy, 0), 127) * 128);
            unsigned short yB = (unsigned short)(min(max(iy + 1, 0), 127) * 128);
            s_tabi[k * 256 + tid] = make_ushort4(xA, xB, yA, yB);
        }
    }

    float acc[16][4];
#pragma unroll
    for (int o = 0; o < 16; o++)
#pragma unroll
        for (int p = 0; p < 4; p++) acc[o][p] = 0.f;

    const int q   = tid & 63;          // pixel-quad id (4 px each)
    const int ocb = (tid >> 6) * 16;   // 16 oc per thread

    for (int cb = 0; cb < 64; cb += 4) {
        __syncthreads();   // protect s_samp/s_w vs previous GEMM reads; also orders Phase A

        // weight chunk: s_w[ck][oc], ck = ci*9 + k
#pragma unroll
        for (int i = 0; i < 9; i++) {
            int idx = i * 256 + tid;
            int ck = idx >> 6;
            int oc = idx & 63;
            int ci = ck / 9;
            int k  = ck - ci * 9;
            s_w[idx] = __ldg(&wgt[oc * 576 + (cb + ci) * 9 + k]);
        }

        // gather: tab reused across the 4 channels of the chunk
        const float* xb = xin + ((size_t)b * 64 + cb) * HWSZ;
#pragma unroll 3
        for (int k = 0; k < 9; k++) {
            float4  w4 = ((float4*)s_tabw)[k * 256 + tid];
            ushort4 t  = s_tabi[k * 256 + tid];
            int iA = (int)t.z + (int)t.x;
            int iB = (int)t.z + (int)t.y;
            int iC = (int)t.w + (int)t.x;
            int iD = (int)t.w + (int)t.y;
#pragma unroll
            for (int ci = 0; ci < 4; ci++) {
                const float* p = xb + ci * HWSZ;
                float v = w4.x * __ldg(p + iA) + w4.y * __ldg(p + iB)
                        + w4.z * __ldg(p + iC) + w4.w * __ldg(p + iD);
                s_samp[(ci * 9 + k) * 256 + tid] = v;
            }
        }
        __syncthreads();

        // GEMM: 36 ck-steps, 16 oc x 4 px per thread
#pragma unroll 4
        for (int ck = 0; ck < 36; ck++) {
            float4 s4 = ((const float4*)(s_samp + ck * 256))[q];
            const float* wr = s_w + ck * 64 + ocb;
            float4 wv0 = *(const float4*)(wr);
            float4 wv1 = *(const float4*)(wr + 4);
            float4 wv2 = *(const float4*)(wr + 8);
            float4 wv3 = *(const float4*)(wr + 12);
            float sv[4] = {s4.x, s4.y, s4.z, s4.w};
            float wf[16] = {wv0.x, wv0.y, wv0.z, wv0.w,
                            wv1.x, wv1.y, wv1.z, wv1.w,
                            wv2.x, wv2.y, wv2.z, wv2.w,
                            wv3.x, wv3.y, wv3.z, wv3.w};
#pragma unroll
            for (int o = 0; o < 16; o++)
#pragma unroll
                for (int p = 0; p < 4; p++)
                    acc[o][p] = fmaf(sv[p], wf[o], acc[o][p]);
        }
    }

    // epilogue: bias + lrelu, coalesced float4 stores
    const int px0 = q * 4;
    const int x = px0 & 127;
    const int y = row0 + (px0 >> 7);
#pragma unroll
    for (int o = 0; o < 16; o++) {
        int gc = ocb + o;
        float bv = __ldg(&bias[gc]);
        float r[4];
#pragma unroll
        for (int p = 0; p < 4; p++) {
            float v = acc[o][p] + bv;
            r[p] = (v >= 0.f) ? v : 0.1f * v;
        }
        *(float4*)&out[((b * 64 + gc) * HH + y) * WW + x] =
            make_float4(r[0], r[1], r[2], r[3]);
    }
}

extern "C" void kernel_launch(void* const* d_in, const int* in_sizes, int n_in,
                              void* d_out, int out_size)
{
    const float* nbr   = (const float*)d_in[0];
    const float* ref   = (const float*)d_in[1];
    const float* w1    = (const float*)d_in[2];
    const float* b1    = (const float*)d_in[3];
    const float* w2    = (const float*)d_in[4];
    const float* b2    = (const float*)d_in[5];
    const float* w3    = (const float*)d_in[6];
    const float* b3    = (const float*)d_in[7];
    const float* w_off = (const float*)d_in[8];
    const float* b_off = (const float*)d_in[9];
    const float* w_dcn = (const float*)d_in[10];
    const float* b_dcn = (const float*)d_in[11];

    float* out  = (float*)d_out;
    float* feat = out;                              // [B,64,H,W]
    float* offp = out + (size_t)BB * 64 * HWSZ;     // [B,18,H,W]
    float* mskp = offp + (size_t)BB * 18 * HWSZ;    // [B,9,H,W]

    float *bufA = nullptr, *bufB = nullptr;
    cudaGetSymbolAddress((void**)&bufA, g_bufA);
    cudaGetSymbolAddress((void**)&bufB, g_bufB);

    const int dcn_smem = 101376;
    cudaFuncSetAttribute(dcn_gemm_k, cudaFuncAttributeMaxDynamicSharedMemorySize, dcn_smem);

    dim3 cblk(8, 16);
    // conv1: concat(nbr, ref) 128 -> 64, lrelu
    conv3x3_k<<<dim3(4, 8, BB * 8), cblk>>>(nbr, ref, 128, w1, b1, bufA, 64, 0, nullptr, nullptr);
    // conv2: 64 -> 64, lrelu
    conv3x3_k<<<dim3(4, 8, BB * 8), cblk>>>(bufA, nullptr, 64, w2, b2, bufB, 64, 0, nullptr, nullptr);
    // conv3: 64 -> 64, lrelu
    conv3x3_k<<<dim3(4, 8, BB * 8), cblk>>>(bufB, nullptr, 64, w3, b3, bufA, 64, 0, nullptr, nullptr);
    // conv_off: 64 -> 27, split into offset (15*tanh) and mask (sigmoid), to d_out
    conv3x3_k<<<dim3(4, 8, BB * 4), cblk>>>(bufA, nullptr, 64, w_off, b_off, nullptr, 27, 1, offp, mskp);
    // DCNv2 (implicit GEMM) on nbr with offsets/mask from d_out, lrelu -> feat
    dcn_gemm_k<<<dim3(HH / 2, BB), 256, dcn_smem>>>(nbr, offp, mskp, w_dcn, b_dcn, feat);
}

// round 12
// speedup vs baseline: 1.3649x; 1.3649x over previous
#include <cuda_runtime.h>
#include <math.h>

#define HH 128
#define WW 128
#define HWSZ (HH*WW)
#define NFC 64
#define BB 4

// Scratch ping-pong buffers (no allocation allowed)
__device__ float g_bufA[BB*NFC*HWSZ];
__device__ float g_bufB[BB*NFC*HWSZ];

// ---------------------------------------------------------------------------
// Tiled 3x3 conv, stride 1, pad 1.
// Tile: 32x32 spatial, 256 threads, 8 oc per block, 4 px per thread (x),
// 8-ci smem chunks. Doubled warps/block vs R6 to fix grid-limited occupancy.
// mode 0: lrelu -> out; mode 1: offsets (15*tanh) / mask (sigmoid) split.
// ---------------------------------------------------------------------------
__global__ __launch_bounds__(256) void conv3x3_k(
    const float* __restrict__ in0, const float* __restrict__ in1, int cin,
    const float* __restrict__ wgt, const float* __restrict__ bias,
    float* __restrict__ out, int cout, int mode,
    float* __restrict__ outOff, float* __restrict__ outMask)
{
    __shared__ float s_in[8][34][34];   // [ci][row 32+2][col 32+2]
    __shared__ float s_w[8][8][9];      // [oc][ci][k]

    const int tx = threadIdx.x;         // 0..7
    const int ty = threadIdx.y;         // 0..31
    const int tid = ty * 8 + tx;
    const int x0 = blockIdx.x * 32;
    const int y0 = blockIdx.y * 32;
    const int groups = (cout + 7) / 8;
    const int b = blockIdx.z / groups;
    const int ocBase = (blockIdx.z % groups) * 8;

    float acc[8][4];
#pragma unroll
    for (int o = 0; o < 8; o++)
#pragma unroll
        for (int p = 0; p < 4; p++) acc[o][p] = 0.f;

    for (int cb = 0; cb < cin; cb += 8) {
        __syncthreads();
        // load input tile (8 channels, 34x34 with halo, zero padded)
        for (int idx = tid; idx < 8 * 1156; idx += 256) {
            int ci = idx / 1156;
            int rem = idx - ci * 1156;
            int r = rem / 34;
            int c = rem - r * 34;
            int gy = y0 + r - 1;
            int gx = x0 + c - 1;
            int ch = cb + ci;
            const float* src = in0;
            int chl = ch;
            if (ch >= 64) { src = in1; chl = ch - 64; }
            float v = 0.f;
            if (gy >= 0 && gy < HH && gx >= 0 && gx < WW)
                v = __ldg(&src[((b * 64 + chl) * HH + gy) * WW + gx]);
            (&s_in[0][0][0])[idx] = v;
        }
        // load weights for this (oc block, ci chunk)
        for (int idx = tid; idx < 8 * 8 * 9; idx += 256) {
            int oc = idx / 72;
            int rem = idx - oc * 72;
            int ci = rem / 9;
            int k = rem - ci * 9;
            int gc = ocBase + oc;
            float v = 0.f;
            if (gc < cout) v = __ldg(&wgt[(gc * cin + cb + ci) * 9 + k]);
            (&s_w[0][0][0])[idx] = v;
        }
        __syncthreads();

#pragma unroll 2
        for (int ci = 0; ci < 8; ci++) {
            float v[3][6];
#pragma unroll
            for (int r = 0; r < 3; r++)
#pragma unroll
                for (int c = 0; c < 6; c++)
                    v[r][c] = s_in[ci][ty + r][tx * 4 + c];
#pragma unroll
            for (int oc = 0; oc < 8; oc++) {
#pragma unroll
                for (int kr = 0; kr < 3; kr++)
#pragma unroll
                    for (int kc = 0; kc < 3; kc++) {
                        float wv = s_w[oc][ci][kr * 3 + kc];
#pragma unroll
                        for (int p = 0; p < 4; p++)
                            acc[oc][p] = fmaf(v[kr][kc + p], wv, acc[oc][p]);
                    }
            }
        }
    }

    const int y = y0 + ty;
    const int xb = x0 + tx * 4;
#pragma unroll
    for (int oc = 0; oc < 8; oc++) {
        int gc = ocBase + oc;
        if (gc >= cout) continue;
        float bv = __ldg(&bias[gc]);
        float r[4];
#pragma unroll
        for (int p = 0; p < 4; p++) r[p] = acc[oc][p] + bv;
        if (mode == 0) {
#pragma unroll
            for (int p = 0; p < 4; p++) r[p] = (r[p] >= 0.f) ? r[p] : 0.1f * r[p];
            float4 v4 = make_float4(r[0], r[1], r[2], r[3]);
            *(float4*)&out[((b * cout + gc) * HH + y) * WW + xb] = v4;
        } else {
            if (gc < 18) {
#pragma unroll
                for (int p = 0; p < 4; p++) r[p] = 15.f * tanhf(r[p]);
                float4 v4 = make_float4(r[0], r[1], r[2], r[3]);
                *(float4*)&outOff[((b * 18 + gc) * HH + y) * WW + xb] = v4;
            } else {
#pragma unroll
                for (int p = 0; p < 4; p++) r[p] = 1.f / (1.f + expf(-r[p]));
                float4 v4 = make_float4(r[0], r[1], r[2], r[3]);
                *(float4*)&outMask[((b * 9 + (gc - 18)) * HH + y) * WW + xb] = v4;
            }
        }
    }
}

// ---------------------------------------------------------------------------
// DCNv2 as smem-staged implicit GEMM. One block = 1 row x 128 px x 64 oc.
// 128 threads; thread = 16 oc x 4 px. Per 4-ci chunk:
//   - weights loaded COALESCED (float4 along wgt layout), transposed via STS
//     into s_w[ck*68 + oc] (pad 68 keeps stores ~2-way, GEMM reads broadcast)
//   - cooperative gather (bilinear tables built once) -> s_samp[36][128]
//   - register-tiled GEMM, 36 ck-steps.
// smem 55872 B -> 4 blocks/SM; grid 512.
// ---------------------------------------------------------------------------
__global__ __launch_bounds__(128, 4) void dcn_gemm_k(
    const float* __restrict__ xin, const float* __restrict__ off,
    const float* __restrict__ msk, const float* __restrict__ wgt,
    const float* __restrict__ bias, float* __restrict__ out)
{
    extern __shared__ float sm[];
    float*   s_tabw = sm;                          // 9*128 float4  = 18432 B
    ushort4* s_tabi = (ushort4*)(sm + 4608);       // 9*128 ushort4 =  9216 B
    float*   s_samp = sm + 4608 + 2304;            // 36*128 floats = 18432 B
    float*   s_w    = s_samp + 4608;               // 36*68 floats  =  9792 B

    const int tid = threadIdx.x;       // 0..127
    const int b   = blockIdx.y;
    const int y   = blockIdx.x;        // one image row per block

    // ---- Phase A: bilinear tables (x = tid), 9 taps
    {
        const int x = tid;
#pragma unroll
        for (int k = 0; k < 9; k++) {
            float oy = __ldg(&off[((b * 18 + 2 * k) * HH + y) * WW + x]);
            float ox = __ldg(&off[((b * 18 + 2 * k + 1) * HH + y) * WW + x]);
            float m  = __ldg(&msk[((b * 9 + k) * HH + y) * WW + x]);
            float py  = (float)(y + k / 3 - 1) + oy;
            float pxf = (float)(x + k % 3 - 1) + ox;
            float fy = floorf(py);
            float fx = floorf(pxf);
            float wy = py - fy;
            float wx = pxf - fx;
            int iy = (int)fy;
            int ix = (int)fx;
            bool vy0 = ((unsigned)iy) < 128u;
            bool vy1 = ((unsigned)(iy + 1)) < 128u;
            bool vx0 = ((unsigned)ix) < 128u;
            bool vx1 = ((unsigned)(ix + 1)) < 128u;
            float w00 = (1.f - wy) * (1.f - wx) * m;
            float w01 = (1.f - wy) * wx * m;
            float w10 = wy * (1.f - wx) * m;
            float w11 = wy * wx * m;
            if (!(vy0 && vx0)) w00 = 0.f;
            if (!(vy0 && vx1)) w01 = 0.f;
            if (!(vy1 && vx0)) w10 = 0.f;
            if (!(vy1 && vx1)) w11 = 0.f;
            ((float4*)s_tabw)[k * 128 + tid] = make_float4(w00, w01, w10, w11);
            unsigned short xA = (unsigned short)min(max(ix, 0), 127);
            unsigned short xB = (unsigned short)min(max(ix + 1, 0), 127);
            unsigned short yA = (unsigned short)(min(max(iy, 0), 127) * 128);
            unsigned short yB = (unsigned short)(min(max(iy + 1, 0), 127) * 128);
            s_tabi[k * 128 + tid] = make_ushort4(xA, xB, yA, yB);
        }
    }

    float acc[16][4];
#pragma unroll
    for (int o = 0; o < 16; o++)
#pragma unroll
        for (int p = 0; p < 4; p++) acc[o][p] = 0.f;

    const int q   = tid & 31;          // pixel-quad id (4 px each)
    const int ocb = (tid >> 5) * 16;   // 16 oc per thread (warp-uniform)

    for (int cb = 0; cb < 64; cb += 4) {
        __syncthreads();   // protects s_samp/s_w reuse; first iter orders Phase A

        // ---- weights: coalesced float4 LDG along wgt layout, transpose via STS.
        // chunk slice per oc is contiguous: wgt[oc*576 + cb*9 + ck], ck in [0,36)
        // = 9 float4 per oc (144B, 16B-aligned). 576 float4 total, 128 threads.
        {
            const float4* wsrc = (const float4*)(wgt + cb * 9);
#pragma unroll
            for (int i = 0; i < 5; i++) {
                int idx4 = i * 128 + tid;          // 0..575 (+pad)
                if (idx4 < 576) {
                    int oc  = idx4 / 9;
                    int ck4 = idx4 - oc * 9;       // float4 index within slice
                    float4 w4 = __ldg(&wsrc[oc * 144 + ck4]);   // 576 floats = 144 float4 per oc row
                    int ck = ck4 * 4;
                    s_w[(ck + 0) * 68 + oc] = w4.x;
                    s_w[(ck + 1) * 68 + oc] = w4.y;
                    s_w[(ck + 2) * 68 + oc] = w4.z;
                    s_w[(ck + 3) * 68 + oc] = w4.w;
                }
            }
        }

        // ---- gather: tables reused across the 4 channels of the chunk
        const float* xb = xin + ((size_t)b * 64 + cb) * HWSZ;
#pragma unroll 3
        for (int k = 0; k < 9; k++) {
            float4  w4 = ((float4*)s_tabw)[k * 128 + tid];
            ushort4 t  = s_tabi[k * 128 + tid];
            int iA = (int)t.z + (int)t.x;
            int iB = (int)t.z + (int)t.y;
            int iC = (int)t.w + (int)t.x;
            int iD = (int)t.w + (int)t.y;
#pragma unroll
            for (int ci = 0; ci < 4; ci++) {
                const float* p = xb + ci * HWSZ;
                float v = w4.x * __ldg(p + iA) + w4.y * __ldg(p + iB)
                        + w4.z * __ldg(p + iC) + w4.w * __ldg(p + iD);
                s_samp[(ci * 9 + k) * 128 + tid] = v;
            }
        }
        __syncthreads();

        // ---- GEMM: 36 ck-steps, 16 oc x 4 px per thread
#pragma unroll 6
        for (int ck = 0; ck < 36; ck++) {
            float4 s4 = ((const float4*)(s_samp + ck * 128))[q];
            const float* wr = s_w + ck * 68 + ocb;
            float4 wv0 = *(const float4*)(wr);
            float4 wv1 = *(const float4*)(wr + 4);
            float4 wv2 = *(const float4*)(wr + 8);
            float4 wv3 = *(const float4*)(wr + 12);
            float sv[4] = {s4.x, s4.y, s4.z, s4.w};
            float wf[16] = {wv0.x, wv0.y, wv0.z, wv0.w,
                            wv1.x, wv1.y, wv1.z, wv1.w,
                            wv2.x, wv2.y, wv2.z, wv2.w,
                            wv3.x, wv3.y, wv3.z, wv3.w};
#pragma unroll
            for (int o = 0; o < 16; o++)
#pragma unroll
                for (int p = 0; p < 4; p++)
                    acc[o][p] = fmaf(sv[p], wf[o], acc[o][p]);
        }
    }

    // ---- epilogue: bias + lrelu, coalesced float4 stores
    const int x = q * 4;
#pragma unroll
    for (int o = 0; o < 16; o++) {
        int gc = ocb + o;
        float bv = __ldg(&bias[gc]);
        float r[4];
#pragma unroll
        for (int p = 0; p < 4; p++) {
            float v = acc[o][p] + bv;
            r[p] = (v >= 0.f) ? v : 0.1f * v;
        }
        *(float4*)&out[((b * 64 + gc) * HH + y) * WW + x] =
            make_float4(r[0], r[1], r[2], r[3]);
    }
}

extern "C" void kernel_launch(void* const* d_in, const int* in_sizes, int n_in,
                              void* d_out, int out_size)
{
    const float* nbr   = (const float*)d_in[0];
    const float* ref   = (const float*)d_in[1];
    const float* w1    = (const float*)d_in[2];
    const float* b1    = (const float*)d_in[3];
    const float* w2    = (const float*)d_in[4];
    const float* b2    = (const float*)d_in[5];
    const float* w3    = (const float*)d_in[6];
    const float* b3    = (const float*)d_in[7];
    const float* w_off = (const float*)d_in[8];
    const float* b_off = (const float*)d_in[9];
    const float* w_dcn = (const float*)d_in[10];
    const float* b_dcn = (const float*)d_in[11];

    float* out  = (float*)d_out;
    float* feat = out;                              // [B,64,H,W]
    float* offp = out + (size_t)BB * 64 * HWSZ;     // [B,18,H,W]
    float* mskp = offp + (size_t)BB * 18 * HWSZ;    // [B,9,H,W]

    float *bufA = nullptr, *bufB = nullptr;
    cudaGetSymbolAddress((void**)&bufA, g_bufA);
    cudaGetSymbolAddress((void**)&bufB, g_bufB);

    const int dcn_smem = 55872;
    cudaFuncSetAttribute(dcn_gemm_k, cudaFuncAttributeMaxDynamicSharedMemorySize, dcn_smem);

    dim3 cblk(8, 32);
    // conv1: concat(nbr, ref) 128 -> 64, lrelu
    conv3x3_k<<<dim3(4, 4, BB * 8), cblk>>>(nbr, ref, 128, w1, b1, bufA, 64, 0, nullptr, nullptr);
    // conv2: 64 -> 64, lrelu
    conv3x3_k<<<dim3(4, 4, BB * 8), cblk>>>(bufA, nullptr, 64, w2, b2, bufB, 64, 0, nullptr, nullptr);
    // conv3: 64 -> 64, lrelu
    conv3x3_k<<<dim3(4, 4, BB * 8), cblk>>>(bufB, nullptr, 64, w3, b3, bufA, 64, 0, nullptr, nullptr);
    // conv_off: 64 -> 27, offsets (15*tanh) + mask (sigmoid), to d_out
    conv3x3_k<<<dim3(4, 4, BB * 4), cblk>>>(bufA, nullptr, 64, w_off, b_off, nullptr, 27, 1, offp, mskp);
    // DCNv2 (implicit GEMM) on nbr with offsets/mask from d_out, lrelu -> feat
    dcn_gemm_k<<<dim3(HH, BB), 128, dcn_smem>>>(nbr, offp, mskp, w_dcn, b_dcn, feat);
}

// round 13
// speedup vs baseline: 1.8106x; 1.3265x over previous
#include <cuda_runtime.h>
#include <math.h>

#define HH 128
#define WW 128
#define HWSZ (HH*WW)
#define NFC 64
#define BB 4

// Scratch ping-pong buffers (no allocation allowed)
__device__ float g_bufA[BB*NFC*HWSZ];
__device__ float g_bufB[BB*NFC*HWSZ];

// Trivial kernel: shifts ncu's -s 5 window so launch #5 is dcn_gemm_k.
__global__ void sched_warm_k() {}

// ---------------------------------------------------------------------------
// Tiled 3x3 conv, stride 1, pad 1.  (exact R6 config: 32x16 tile, 128 thr,
// 8 oc/block — measured-best conv variant, conv1=122us)
// mode 0: lrelu -> out; mode 1: offsets (15*tanh) / mask (sigmoid) split.
// ---------------------------------------------------------------------------
__global__ __launch_bounds__(128) void conv3x3_k(
    const float* __restrict__ in0, const float* __restrict__ in1, int cin,
    const float* __restrict__ wgt, const float* __restrict__ bias,
    float* __restrict__ out, int cout, int mode,
    float* __restrict__ outOff, float* __restrict__ outMask)
{
    __shared__ float s_in[8][18][34];   // [ci][row 16+2][col 32+2]
    __shared__ float s_w[8][8][9];      // [oc][ci][k]

    const int tx = threadIdx.x;         // 0..7
    const int ty = threadIdx.y;         // 0..15
    const int tid = ty * 8 + tx;
    const int x0 = blockIdx.x * 32;
    const int y0 = blockIdx.y * 16;
    const int groups = (cout + 7) / 8;
    const int b = blockIdx.z / groups;
    const int ocBase = (blockIdx.z % groups) * 8;

    float acc[8][4];
#pragma unroll
    for (int o = 0; o < 8; o++)
#pragma unroll
        for (int p = 0; p < 4; p++) acc[o][p] = 0.f;

    for (int cb = 0; cb < cin; cb += 8) {
        __syncthreads();
        for (int idx = tid; idx < 8 * 612; idx += 128) {
            int ci = idx / 612;
            int rem = idx % 612;
            int r = rem / 34;
            int c = rem % 34;
            int gy = y0 + r - 1;
            int gx = x0 + c - 1;
            int ch = cb + ci;
            const float* src = in0;
            int chl = ch;
            if (ch >= 64) { src = in1; chl = ch - 64; }
            float v = 0.f;
            if (gy >= 0 && gy < HH && gx >= 0 && gx < WW)
                v = __ldg(&src[((b * 64 + chl) * HH + gy) * WW + gx]);
            (&s_in[0][0][0])[idx] = v;
        }
        for (int idx = tid; idx < 8 * 8 * 9; idx += 128) {
            int oc = idx / 72;
            int rem = idx % 72;
            int ci = rem / 9;
            int k = rem % 9;
            int gc = ocBase + oc;
            float v = 0.f;
            if (gc < cout) v = __ldg(&wgt[(gc * cin + cb + ci) * 9 + k]);
            (&s_w[0][0][0])[idx] = v;
        }
        __syncthreads();

#pragma unroll 2
        for (int ci = 0; ci < 8; ci++) {
            float v[3][6];
#pragma unroll
            for (int r = 0; r < 3; r++)
#pragma unroll
                for (int c = 0; c < 6; c++)
                    v[r][c] = s_in[ci][ty + r][tx * 4 + c];
#pragma unroll
            for (int oc = 0; oc < 8; oc++) {
#pragma unroll
                for (int kr = 0; kr < 3; kr++)
#pragma unroll
                    for (int kc = 0; kc < 3; kc++) {
                        float wv = s_w[oc][ci][kr * 3 + kc];
#pragma unroll
                        for (int p = 0; p < 4; p++)
                            acc[oc][p] = fmaf(v[kr][kc + p], wv, acc[oc][p]);
                    }
            }
        }
    }

    const int y = y0 + ty;
    const int xb = x0 + tx * 4;
#pragma unroll
    for (int oc = 0; oc < 8; oc++) {
        int gc = ocBase + oc;
        if (gc >= cout) continue;
        float bv = __ldg(&bias[gc]);
        float r[4];
#pragma unroll
        for (int p = 0; p < 4; p++) r[p] = acc[oc][p] + bv;
        if (mode == 0) {
#pragma unroll
            for (int p = 0; p < 4; p++) r[p] = (r[p] >= 0.f) ? r[p] : 0.1f * r[p];
            float4 v4 = make_float4(r[0], r[1], r[2], r[3]);
            *(float4*)&out[((b * cout + gc) * HH + y) * WW + xb] = v4;
        } else {
            if (gc < 18) {
#pragma unroll
                for (int p = 0; p < 4; p++) r[p] = 15.f * tanhf(r[p]);
                float4 v4 = make_float4(r[0], r[1], r[2], r[3]);
                *(float4*)&outOff[((b * 18 + gc) * HH + y) * WW + xb] = v4;
            } else {
#pragma unroll
                for (int p = 0; p < 4; p++) r[p] = 1.f / (1.f + expf(-r[p]));
                float4 v4 = make_float4(r[0], r[1], r[2], r[3]);
                *(float4*)&outMask[((b * 9 + (gc - 18)) * HH + y) * WW + xb] = v4;
            }
        }
    }
}

// ---------------------------------------------------------------------------
// DCNv2 implicit GEMM. Block = 1 row x 128 px x 64 oc, 256 threads.
// Thread = 16 oc x 2 px (vs 4 px @128thr before): doubles warps/block ->
// 24 warps/SM (3 blocks x 8 warps), better gather-latency hiding.
// Per 4-ci chunk: coalesced weight load + transpose; cooperative gather
// (tables built once) -> s_samp[36][128]; register-tiled GEMM.
// smem 55872 B.
// ---------------------------------------------------------------------------
__global__ __launch_bounds__(256, 3) void dcn_gemm_k(
    const float* __restrict__ xin, const float* __restrict__ off,
    const float* __restrict__ msk, const float* __restrict__ wgt,
    const float* __restrict__ bias, float* __restrict__ out)
{
    extern __shared__ float sm[];
    float*   s_tabw = sm;                          // 9*128 float4  = 18432 B
    ushort4* s_tabi = (ushort4*)(sm + 4608);       // 9*128 ushort4 =  9216 B
    float*   s_samp = sm + 4608 + 2304;            // 36*128 floats = 18432 B
    float*   s_w    = s_samp + 4608;               // 36*68 floats  =  9792 B

    const int tid = threadIdx.x;       // 0..255
    const int b   = blockIdx.y;
    const int y   = blockIdx.x;        // one image row per block

    // ---- Phase A: bilinear tables, 1152 (k, px) items over 256 threads
#pragma unroll
    for (int i = 0; i < 5; i++) {
        int e = i * 256 + tid;
        if (e < 1152) {
            int k = e >> 7;
            int x = e & 127;
            float oy = __ldg(&off[((b * 18 + 2 * k) * HH + y) * WW + x]);
            float ox = __ldg(&off[((b * 18 + 2 * k + 1) * HH + y) * WW + x]);
            float m  = __ldg(&msk[((b * 9 + k) * HH + y) * WW + x]);
            float py  = (float)(y + k / 3 - 1) + oy;
            float pxf = (float)(x + k % 3 - 1) + ox;
            float fy = floorf(py);
            float fx = floorf(pxf);
            float wy = py - fy;
            float wx = pxf - fx;
            int iy = (int)fy;
            int ix = (int)fx;
            bool vy0 = ((unsigned)iy) < 128u;
            bool vy1 = ((unsigned)(iy + 1)) < 128u;
            bool vx0 = ((unsigned)ix) < 128u;
            bool vx1 = ((unsigned)(ix + 1)) < 128u;
            float w00 = (1.f - wy) * (1.f - wx) * m;
            float w01 = (1.f - wy) * wx * m;
            float w10 = wy * (1.f - wx) * m;
            float w11 = wy * wx * m;
            if (!(vy0 && vx0)) w00 = 0.f;
            if (!(vy0 && vx1)) w01 = 0.f;
            if (!(vy1 && vx0)) w10 = 0.f;
            if (!(vy1 && vx1)) w11 = 0.f;
            ((float4*)s_tabw)[e] = make_float4(w00, w01, w10, w11);
            unsigned short xA = (unsigned short)min(max(ix, 0), 127);
            unsigned short xB = (unsigned short)min(max(ix + 1, 0), 127);
            unsigned short yA = (unsigned short)(min(max(iy, 0), 127) * 128);
            unsigned short yB = (unsigned short)(min(max(iy + 1, 0), 127) * 128);
            s_tabi[e] = make_ushort4(xA, xB, yA, yB);
        }
    }

    float acc[16][2];
#pragma unroll
    for (int o = 0; o < 16; o++)
#pragma unroll
        for (int p = 0; p < 2; p++) acc[o][p] = 0.f;

    const int q   = tid & 63;          // pixel-pair id (2 px each)
    const int ocb = (tid >> 6) * 16;   // 16 oc per thread (warp-uniform)

    for (int cb = 0; cb < 64; cb += 4) {
        __syncthreads();   // protects s_samp/s_w reuse; first iter orders Phase A

        // ---- weights: coalesced float4 LDG, transpose via STS to s_w[ck*68+oc]
        {
            const float4* wsrc = (const float4*)(wgt + cb * 9);
#pragma unroll
            for (int i = 0; i < 3; i++) {
                int idx4 = i * 256 + tid;          // 0..575
                if (idx4 < 576) {
                    int oc  = idx4 / 9;
                    int ck4 = idx4 - oc * 9;
                    float4 w4 = __ldg(&wsrc[oc * 144 + ck4]);
                    int ck = ck4 * 4;
                    s_w[(ck + 0) * 68 + oc] = w4.x;
                    s_w[(ck + 1) * 68 + oc] = w4.y;
                    s_w[(ck + 2) * 68 + oc] = w4.z;
                    s_w[(ck + 3) * 68 + oc] = w4.w;
                }
            }
        }

        // ---- gather: 1152 (k, px) items, tables reused across 4 channels
        const float* xb = xin + ((size_t)b * 64 + cb) * HWSZ;
#pragma unroll
        for (int i = 0; i < 5; i++) {
            int e = i * 256 + tid;
            if (e < 1152) {
                int k  = e >> 7;
                int px = e & 127;
                float4  w4 = ((float4*)s_tabw)[e];
                ushort4 t  = s_tabi[e];
                int iA = (int)t.z + (int)t.x;
                int iB = (int)t.z + (int)t.y;
                int iC = (int)t.w + (int)t.x;
                int iD = (int)t.w + (int)t.y;
#pragma unroll
                for (int ci = 0; ci < 4; ci++) {
                    const float* p = xb + ci * HWSZ;
                    float v = w4.x * __ldg(p + iA) + w4.y * __ldg(p + iB)
                            + w4.z * __ldg(p + iC) + w4.w * __ldg(p + iD);
                    s_samp[(ci * 9 + k) * 128 + px] = v;
                }
            }
        }
        __syncthreads();

        // ---- GEMM: 36 ck-steps, 16 oc x 2 px per thread
#pragma unroll 6
        for (int ck = 0; ck < 36; ck++) {
            float2 s2 = ((const float2*)(s_samp + ck * 128))[q];
            const float* wr = s_w + ck * 68 + ocb;
            float4 wv0 = *(const float4*)(wr);
            float4 wv1 = *(const float4*)(wr + 4);
            float4 wv2 = *(const float4*)(wr + 8);
            float4 wv3 = *(const float4*)(wr + 12);
            float sv[2] = {s2.x, s2.y};
            float wf[16] = {wv0.x, wv0.y, wv0.z, wv0.w,
                            wv1.x, wv1.y, wv1.z, wv1.w,
                            wv2.x, wv2.y, wv2.z, wv2.w,
                            wv3.x, wv3.y, wv3.z, wv3.w};
#pragma unroll
            for (int o = 0; o < 16; o++)
#pragma unroll
                for (int p = 0; p < 2; p++)
                    acc[o][p] = fmaf(sv[p], wf[o], acc[o][p]);
        }
    }

    // ---- epilogue: bias + lrelu, float2 stores
    const int x = q * 2;
#pragma unroll
    for (int o = 0; o < 16; o++) {
        int gc = ocb + o;
        float bv = __ldg(&bias[gc]);
        float r0 = acc[o][0] + bv;
        float r1 = acc[o][1] + bv;
        r0 = (r0 >= 0.f) ? r0 : 0.1f * r0;
        r1 = (r1 >= 0.f) ? r1 : 0.1f * r1;
        *(float2*)&out[((b * 64 + gc) * HH + y) * WW + x] = make_float2(r0, r1);
    }
}

extern "C" void kernel_launch(void* const* d_in, const int* in_sizes, int n_in,
                              void* d_out, int out_size)
{
    const float* nbr   = (const float*)d_in[0];
    const float* ref   = (const float*)d_in[1];
    const float* w1    = (const float*)d_in[2];
    const float* b1    = (const float*)d_in[3];
    const float* w2    = (const float*)d_in[4];
    const float* b2    = (const float*)d_in[5];
    const float* w3    = (const float*)d_in[6];
    const float* b3    = (const float*)d_in[7];
    const float* w_off = (const float*)d_in[8];
    const float* b_off = (const float*)d_in[9];
    const float* w_dcn = (const float*)d_in[10];
    const float* b_dcn = (const float*)d_in[11];

    float* out  = (float*)d_out;
    float* feat = out;                              // [B,64,H,W]
    float* offp = out + (size_t)BB * 64 * HWSZ;     // [B,18,H,W]
    float* mskp = offp + (size_t)BB * 18 * HWSZ;    // [B,9,H,W]

    float *bufA = nullptr, *bufB = nullptr;
    cudaGetSymbolAddress((void**)&bufA, g_bufA);
    cudaGetSymbolAddress((void**)&bufB, g_bufB);

    const int dcn_smem = 55872;
    cudaFuncSetAttribute(dcn_gemm_k, cudaFuncAttributeMaxDynamicSharedMemorySize, dcn_smem);

    // Launch #0: trivial — makes ncu (-s 5 -c 1) profile dcn_gemm_k (launch #5)
    sched_warm_k<<<1, 32>>>();

    dim3 cblk(8, 16);
    // conv1: concat(nbr, ref) 128 -> 64, lrelu
    conv3x3_k<<<dim3(4, 8, BB * 8), cblk>>>(nbr, ref, 128, w1, b1, bufA, 64, 0, nullptr, nullptr);
    // conv2: 64 -> 64, lrelu
    conv3x3_k<<<dim3(4, 8, BB * 8), cblk>>>(bufA, nullptr, 64, w2, b2, bufB, 64, 0, nullptr, nullptr);
    // conv3: 64 -> 64, lrelu
    conv3x3_k<<<dim3(4, 8, BB * 8), cblk>>>(bufB, nullptr, 64, w3, b3, bufA, 64, 0, nullptr, nullptr);
    // conv_off: 64 -> 27, offsets (15*tanh) + mask (sigmoid), to d_out
    conv3x3_k<<<dim3(4, 8, BB * 4), cblk>>>(bufA, nullptr, 64, w_off, b_off, nullptr, 27, 1, offp, mskp);
    // DCNv2 (implicit GEMM) on nbr with offsets/mask from d_out, lrelu -> feat
    dcn_gemm_k<<<dim3(HH, BB), 256, dcn_smem>>>(nbr, offp, mskp, w_dcn, b_dcn, feat);
}